// round 13
// baseline (speedup 1.0000x reference)
#include <cuda_runtime.h>
#include <cstdint>

#define NN    131072
#define KK    27
#define FINN  3
#define FOUTN 32
#define EPSB  1e-5f

// Scratch: h [N,32] fp32 (16MB); pre-split w2 (tf32 hi/lo), [k][f][g][j] layout
__device__ __align__(256) float g_h[NN * FOUTN];
__device__ __align__(256) float g_w2hi[KK * 32 * 8 * 4];
__device__ __align__(256) float g_w2lo[KK * 32 * 8 * 4];

typedef unsigned long long ull;

__device__ __forceinline__ ull fma2(ull a, ull b, ull c) {
    ull d;
    asm("fma.rn.f32x2 %0, %1, %2, %3;" : "=l"(d) : "l"(a), "l"(b), "l"(c));
    return d;
}
__device__ __forceinline__ ull pack2(float x) {
    ull r; unsigned u = __float_as_uint(x);
    asm("mov.b64 %0, {%1, %2};" : "=l"(r) : "r"(u), "r"(u));
    return r;
}
__device__ __forceinline__ float2 unpack2(ull v) {
    unsigned lo, hi;
    asm("mov.b64 {%0, %1}, %2;" : "=r"(lo), "=r"(hi) : "l"(v));
    return make_float2(__uint_as_float(lo), __uint_as_float(hi));
}
__device__ __forceinline__ unsigned tf32_rn(float v) {
    unsigned r;
    asm("cvt.rna.tf32.f32 %0, %1;" : "=r"(r) : "f"(v));
    return r;
}
__device__ __forceinline__ void split32(float v, unsigned& hi, unsigned& lo) {
    hi = tf32_rn(v);
    lo = tf32_rn(v - __uint_as_float(hi));
}
__device__ __forceinline__ void mma_tf32(float* d,
    unsigned a0, unsigned a1, unsigned a2, unsigned a3,
    unsigned b0, unsigned b1) {
    asm volatile(
        "mma.sync.aligned.m16n8k8.row.col.f32.tf32.tf32.f32 "
        "{%0,%1,%2,%3}, {%4,%5,%6,%7}, {%8,%9}, {%0,%1,%2,%3};"
        : "+f"(d[0]), "+f"(d[1]), "+f"(d[2]), "+f"(d[3])
        : "r"(a0), "r"(a1), "r"(a2), "r"(a3), "r"(b0), "r"(b1));
}

// ============================================================================
// Stage 1: h = silu(bn1(gather(x) @ w1)); blocks 0..26 also pre-split w2[k]
// ============================================================================
__global__ __launch_bounds__(256)
void stage1_kernel(const float* __restrict__ x_feats,
                   const int*   __restrict__ nbr,
                   const float* __restrict__ w1,
                   const float* __restrict__ gamma1,
                   const float* __restrict__ beta1,
                   const float* __restrict__ mean1,
                   const float* __restrict__ var1,
                   const float* __restrict__ w2)
{
    __shared__ __align__(16) float w1s[KK * FINN * FOUTN];
    __shared__ float s_scale[FOUTN], s_shift[FOUTN];

    const int tid = threadIdx.x;

    // side duty: block k<27 splits w2[k] into [f][g][j] hi/lo float4s
    if (blockIdx.x < KK) {
        const int k = blockIdx.x;
        const int f = tid >> 3, g = tid & 7;
        const float* wk = w2 + (size_t)k * 1024 + f * FOUTN;
        float4 hi, lo;
        float v;
        unsigned h, l;
        v = wk[g];      split32(v, h, l); hi.x = __uint_as_float(h); lo.x = __uint_as_float(l);
        v = wk[8 + g];  split32(v, h, l); hi.y = __uint_as_float(h); lo.y = __uint_as_float(l);
        v = wk[16 + g]; split32(v, h, l); hi.z = __uint_as_float(h); lo.z = __uint_as_float(l);
        v = wk[24 + g]; split32(v, h, l); hi.w = __uint_as_float(h); lo.w = __uint_as_float(l);
        const int e = (k * 32 + f) * 8 + g;
        ((float4*)g_w2hi)[e] = hi;
        ((float4*)g_w2lo)[e] = lo;
    }

    for (int i = tid; i < (KK * FINN * FOUTN) / 4; i += blockDim.x)
        ((float4*)w1s)[i] = ((const float4*)w1)[i];
    if (tid < FOUTN) {
        float sc = gamma1[tid] * rsqrtf(var1[tid] + EPSB);
        s_scale[tid] = sc;
        s_shift[tid] = beta1[tid] - mean1[tid] * sc;
    }
    __syncthreads();

    const int n = blockIdx.x * blockDim.x + tid;
    const int* nrow = nbr + (size_t)n * KK;

    ull acc[16];
    #pragma unroll
    for (int i = 0; i < 16; i++) acc[i] = 0ULL;

    int idx_next = nrow[0];
    #pragma unroll 1
    for (int k = 0; k < KK; k++) {
        const int idx = idx_next;
        if (k + 1 < KK) idx_next = nrow[k + 1];
        const float* xr = x_feats + (size_t)idx * FINN;
        float xv[3];
        xv[0] = __ldg(xr); xv[1] = __ldg(xr + 1); xv[2] = __ldg(xr + 2);
        #pragma unroll
        for (int f = 0; f < FINN; f++) {
            ull s2 = pack2(xv[f]);
            const ulonglong2* wp = (const ulonglong2*)(w1s + (k * FINN + f) * FOUTN);
            #pragma unroll
            for (int j = 0; j < 8; j++) {
                ulonglong2 w = wp[j];
                acc[2 * j]     = fma2(s2, w.x, acc[2 * j]);
                acc[2 * j + 1] = fma2(s2, w.y, acc[2 * j + 1]);
            }
        }
    }

    float outv[FOUTN];
    #pragma unroll
    for (int i = 0; i < 16; i++) {
        float2 v = unpack2(acc[i]);
        outv[2 * i] = v.x; outv[2 * i + 1] = v.y;
    }
    float4* dst = (float4*)(g_h + (size_t)n * FOUTN);
    #pragma unroll
    for (int j = 0; j < 8; j++) {
        float4 o4; float v;
        v = outv[4*j+0] * s_scale[4*j+0] + s_shift[4*j+0]; o4.x = v / (1.f + __expf(-v));
        v = outv[4*j+1] * s_scale[4*j+1] + s_shift[4*j+1]; o4.y = v / (1.f + __expf(-v));
        v = outv[4*j+2] * s_scale[4*j+2] + s_shift[4*j+2]; o4.z = v / (1.f + __expf(-v));
        v = outv[4*j+3] * s_scale[4*j+3] + s_shift[4*j+3]; o4.w = v / (1.f + __expf(-v));
        dst[j] = o4;
    }
}

// ============================================================================
// Stage 2 (mma.sync 3xTF32): D[128,32] = sum_k Hgather_k[128,32] @ w2[k]
// B operands pre-split (g_w2hi/lo), fetched as float4 per (fc, half).
// ============================================================================
#define S2T   256
#define TILE  128
#define RST   36
#define OFF_B0  0
#define OFF_B1  4608
#define OFF_IDX 9216
#define OFF_ZW  12672
#define OFF_ZB  12768
#define S2FLOATS 12800
#define S2BYTES  (S2FLOATS * 4)

__global__ __launch_bounds__(S2T, 2)
void stage2_mma(const float* __restrict__ z_feats,
                const int*   __restrict__ nbr,
                const float* __restrict__ mlp_w,
                const float* __restrict__ mlp_b,
                const float* __restrict__ mlp_gamma,
                const float* __restrict__ mlp_beta,
                const float* __restrict__ mlp_mean,
                const float* __restrict__ mlp_var,
                float* __restrict__ out,
                int N, int copies)
{
    extern __shared__ __align__(16) float sm[];
    float* bufA = sm + OFF_B0;
    float* bufB = sm + OFF_B1;
    int*   idxa = (int*)(sm + OFF_IDX);
    float* zw   = sm + OFF_ZW;
    float* zb   = sm + OFF_ZB;

    const int t = threadIdx.x;
    const int base = blockIdx.x * TILE;

    {
        const int4* nb4 = (const int4*)(nbr + (size_t)base * KK);
        #pragma unroll
        for (int i = 0; i < 4; i++) {
            int e = t + i * 256;
            if (e < (TILE * KK) / 4) ((int4*)idxa)[e] = nb4[e];
        }
    }
    if (t < FOUTN) {
        float sc = mlp_gamma[t] * rsqrtf(mlp_var[t] + EPSB);
        float sh = mlp_beta[t] - mlp_mean[t] * sc;
        zb[t] = mlp_b[t] * sc + sh;
        #pragma unroll
        for (int f = 0; f < FINN; f++)
            zw[f * FOUTN + t] = mlp_w[f * FOUTN + t] * sc;
    }
    __syncthreads();

    // gather k=0 into bufA
    #pragma unroll
    for (int p = 0; p < 4; p++) {
        int s = p * 256 + t, r = s >> 3, gs = s & 7;
        int idx = idxa[r * KK];
        float4 v = ((const float4*)(g_h + (size_t)idx * FOUTN))[gs];
        *(float4*)(bufA + r * RST + gs * 4) = v;
    }
    __syncthreads();

    const int w    = t >> 5;
    const int lane = t & 31;
    const int g    = lane >> 2;
    const int tig  = lane & 3;
    const int row0 = w * 16 + g;

    float d[4][4];
    #pragma unroll
    for (int j = 0; j < 4; j++)
        #pragma unroll
        for (int i = 0; i < 4; i++) d[j][i] = 0.f;

    #pragma unroll 1
    for (int k = 0; k < KK; k++) {
        const float* cb = (k & 1) ? bufB : bufA;
        float* nb = (k & 1) ? bufA : bufB;

        // prefetch gather for k+1
        float4 pf[4];
        if (k + 1 < KK) {
            #pragma unroll
            for (int p = 0; p < 4; p++) {
                int s = p * 256 + t, r = s >> 3, gs = s & 7;
                int idx = idxa[r * KK + k + 1];
                pf[p] = ((const float4*)(g_h + (size_t)idx * FOUTN))[gs];
            }
        }

        // compute k
        #pragma unroll
        for (int fc = 0; fc < 4; fc++) {
            const int cbase = fc * 8 + tig;
            float a0f = cb[row0 * RST + cbase];
            float a1f = cb[(row0 + 8) * RST + cbase];
            float a2f = cb[row0 * RST + cbase + 4];
            float a3f = cb[(row0 + 8) * RST + cbase + 4];
            unsigned ah0, al0, ah1, al1, ah2, al2, ah3, al3;
            split32(a0f, ah0, al0); split32(a1f, ah1, al1);
            split32(a2f, ah2, al2); split32(a3f, al2 = 0, al3); // placeholder (overwritten below)
            split32(a3f, ah3, al3);
            // (re-do a2 split cleanly; compiler folds)
            split32(a2f, ah2, al2);

            const int e0 = (k * 32 + cbase) * 8 + g;       // f = cbase
            const int e1 = (k * 32 + cbase + 4) * 8 + g;   // f = cbase+4
            float4 bh0 = __ldg((const float4*)g_w2hi + e0);
            float4 bh1 = __ldg((const float4*)g_w2hi + e1);
            float4 bl0 = __ldg((const float4*)g_w2lo + e0);
            float4 bl1 = __ldg((const float4*)g_w2lo + e1);
            const float* bh0a = &bh0.x; const float* bh1a = &bh1.x;
            const float* bl0a = &bl0.x; const float* bl1a = &bl1.x;
            #pragma unroll
            for (int j = 0; j < 4; j++) {
                unsigned b0h = __float_as_uint(bh0a[j]);
                unsigned b1h = __float_as_uint(bh1a[j]);
                unsigned b0l = __float_as_uint(bl0a[j]);
                unsigned b1l = __float_as_uint(bl1a[j]);
                mma_tf32(d[j], ah0, ah1, ah2, ah3, b0h, b1h);
                mma_tf32(d[j], ah0, ah1, ah2, ah3, b0l, b1l);
                mma_tf32(d[j], al0, al1, al2, al3, b0h, b1h);
            }
        }

        if (k + 1 < KK) {
            #pragma unroll
            for (int p = 0; p < 4; p++) {
                int s = p * 256 + t, r = s >> 3, gs = s & 7;
                *(float4*)(nb + r * RST + gs * 4) = pf[p];
            }
        }
        __syncthreads();
    }

    // epilogue
    const int n0 = base + row0;
    const int n1 = n0 + 8;
    const float* zr0 = z_feats + (size_t)n0 * FINN;
    const float* zr1 = z_feats + (size_t)n1 * FINN;
    float z00 = zr0[0], z01 = zr0[1], z02 = zr0[2];
    float z10 = zr1[0], z11 = zr1[1], z12 = zr1[2];

    #pragma unroll
    for (int j = 0; j < 4; j++) {
        int c = 8 * j + 2 * tig;
        float zw0c = zw[c],     zw1c = zw[FOUTN + c],     zw2c = zw[2*FOUTN + c],     zbc = zb[c];
        float zw0d = zw[c + 1], zw1d = zw[FOUTN + c + 1], zw2d = zw[2*FOUTN + c + 1], zbd = zb[c + 1];

        float2 o0, o1;
        o0.x = d[j][0] + fmaxf(z00 * zw0c + z01 * zw1c + z02 * zw2c + zbc, 0.f);
        o0.y = d[j][1] + fmaxf(z00 * zw0d + z01 * zw1d + z02 * zw2d + zbd, 0.f);
        o1.x = d[j][2] + fmaxf(z10 * zw0c + z11 * zw1c + z12 * zw2c + zbc, 0.f);
        o1.y = d[j][3] + fmaxf(z10 * zw0d + z11 * zw1d + z12 * zw2d + zbd, 0.f);

        *(float2*)(out + (size_t)n0 * FOUTN + c) = o0;
        *(float2*)(out + (size_t)n1 * FOUTN + c) = o1;
        if (copies > 1) {
            *(float2*)(out + (size_t)N * FOUTN + (size_t)n0 * FOUTN + c) = o0;
            *(float2*)(out + (size_t)N * FOUTN + (size_t)n1 * FOUTN + c) = o1;
        }
    }
}

extern "C" void kernel_launch(void* const* d_in, const int* in_sizes, int n_in,
                              void* d_out, int out_size) {
    const float* x_feats   = (const float*)d_in[0];
    const float* z_feats   = (const float*)d_in[1];
    const int*   nbr       = (const int*)d_in[2];
    const float* w1        = (const float*)d_in[3];
    const float* bn1_gamma = (const float*)d_in[4];
    const float* bn1_beta  = (const float*)d_in[5];
    const float* bn1_mean  = (const float*)d_in[6];
    const float* bn1_var   = (const float*)d_in[7];
    const float* w2        = (const float*)d_in[8];
    const float* mlp_w     = (const float*)d_in[9];
    const float* mlp_b     = (const float*)d_in[10];
    const float* mlp_gamma = (const float*)d_in[11];
    const float* mlp_beta  = (const float*)d_in[12];
    const float* mlp_mean  = (const float*)d_in[13];
    const float* mlp_var   = (const float*)d_in[14];

    const int N = in_sizes[0] / FINN;
    const int copies = out_size / (N * FOUTN);

    static int cfg_done = 0;
    if (!cfg_done) {
        (void)cudaFuncSetAttribute(stage2_mma,
                                   cudaFuncAttributeMaxDynamicSharedMemorySize,
                                   S2BYTES);
        cfg_done = 1;
    }

    stage1_kernel<<<N / 256, 256>>>(x_feats, nbr, w1,
                                    bn1_gamma, bn1_beta, bn1_mean, bn1_var, w2);
    stage2_mma<<<N / TILE, S2T, S2BYTES>>>(z_feats, nbr,
                                           mlp_w, mlp_b, mlp_gamma, mlp_beta,
                                           mlp_mean, mlp_var,
                                           (float*)d_out, N, copies);
}

// round 14
// speedup vs baseline: 1.3685x; 1.3685x over previous
#include <cuda_runtime.h>
#include <cstdint>

#define NN    131072
#define KK    27
#define FINN  3
#define FOUTN 32
#define EPSB  1e-5f

// Scratch: h [N,32] fp32 (16MB); pre-split w2 (tf32 hi/lo), [k][f][g][j] layout
__device__ __align__(256) float g_h[NN * FOUTN];
__device__ __align__(256) float g_w2hi[KK * 32 * 8 * 4];
__device__ __align__(256) float g_w2lo[KK * 32 * 8 * 4];

typedef unsigned long long ull;

__device__ __forceinline__ ull fma2(ull a, ull b, ull c) {
    ull d;
    asm("fma.rn.f32x2 %0, %1, %2, %3;" : "=l"(d) : "l"(a), "l"(b), "l"(c));
    return d;
}
__device__ __forceinline__ ull pack2(float x) {
    ull r; unsigned u = __float_as_uint(x);
    asm("mov.b64 %0, {%1, %2};" : "=l"(r) : "r"(u), "r"(u));
    return r;
}
__device__ __forceinline__ float2 unpack2(ull v) {
    unsigned lo, hi;
    asm("mov.b64 {%0, %1}, %2;" : "=r"(lo), "=r"(hi) : "l"(v));
    return make_float2(__uint_as_float(lo), __uint_as_float(hi));
}
__device__ __forceinline__ unsigned tf32_rn(float v) {
    unsigned r;
    asm("cvt.rna.tf32.f32 %0, %1;" : "=r"(r) : "f"(v));
    return r;
}
__device__ __forceinline__ void split32(float v, unsigned& hi, unsigned& lo) {
    hi = tf32_rn(v);
    lo = tf32_rn(v - __uint_as_float(hi));
}
__device__ __forceinline__ void mma_tf32(float* d,
    unsigned a0, unsigned a1, unsigned a2, unsigned a3,
    unsigned b0, unsigned b1) {
    asm volatile(
        "mma.sync.aligned.m16n8k8.row.col.f32.tf32.tf32.f32 "
        "{%0,%1,%2,%3}, {%4,%5,%6,%7}, {%8,%9}, {%0,%1,%2,%3};"
        : "+f"(d[0]), "+f"(d[1]), "+f"(d[2]), "+f"(d[3])
        : "r"(a0), "r"(a1), "r"(a2), "r"(a3), "r"(b0), "r"(b1));
}

// ============================================================================
// Stage 1: h = silu(bn1(gather(x) @ w1)); blocks 0..26 also pre-split w2[k]
// ============================================================================
__global__ __launch_bounds__(256)
void stage1_kernel(const float* __restrict__ x_feats,
                   const int*   __restrict__ nbr,
                   const float* __restrict__ w1,
                   const float* __restrict__ gamma1,
                   const float* __restrict__ beta1,
                   const float* __restrict__ mean1,
                   const float* __restrict__ var1,
                   const float* __restrict__ w2)
{
    __shared__ __align__(16) float w1s[KK * FINN * FOUTN];
    __shared__ float s_scale[FOUTN], s_shift[FOUTN];

    const int tid = threadIdx.x;

    // side duty: block k<27 splits w2[k] into [f][g][j] hi/lo float4s
    if (blockIdx.x < KK) {
        const int k = blockIdx.x;
        const int f = tid >> 3, g = tid & 7;
        const float* wk = w2 + (size_t)k * 1024 + f * FOUTN;
        float4 hi, lo;
        float v; unsigned h, l;
        v = wk[g];      split32(v, h, l); hi.x = __uint_as_float(h); lo.x = __uint_as_float(l);
        v = wk[8 + g];  split32(v, h, l); hi.y = __uint_as_float(h); lo.y = __uint_as_float(l);
        v = wk[16 + g]; split32(v, h, l); hi.z = __uint_as_float(h); lo.z = __uint_as_float(l);
        v = wk[24 + g]; split32(v, h, l); hi.w = __uint_as_float(h); lo.w = __uint_as_float(l);
        const int e = (k * 32 + f) * 8 + g;
        ((float4*)g_w2hi)[e] = hi;
        ((float4*)g_w2lo)[e] = lo;
    }

    for (int i = tid; i < (KK * FINN * FOUTN) / 4; i += blockDim.x)
        ((float4*)w1s)[i] = ((const float4*)w1)[i];
    if (tid < FOUTN) {
        float sc = gamma1[tid] * rsqrtf(var1[tid] + EPSB);
        s_scale[tid] = sc;
        s_shift[tid] = beta1[tid] - mean1[tid] * sc;
    }
    __syncthreads();

    const int n = blockIdx.x * blockDim.x + tid;
    const int* nrow = nbr + (size_t)n * KK;

    ull acc[16];
    #pragma unroll
    for (int i = 0; i < 16; i++) acc[i] = 0ULL;

    int idx_next = nrow[0];
    #pragma unroll 1
    for (int k = 0; k < KK; k++) {
        const int idx = idx_next;
        if (k + 1 < KK) idx_next = nrow[k + 1];
        const float* xr = x_feats + (size_t)idx * FINN;
        float xv[3];
        xv[0] = __ldg(xr); xv[1] = __ldg(xr + 1); xv[2] = __ldg(xr + 2);
        #pragma unroll
        for (int f = 0; f < FINN; f++) {
            ull s2 = pack2(xv[f]);
            const ulonglong2* wp = (const ulonglong2*)(w1s + (k * FINN + f) * FOUTN);
            #pragma unroll
            for (int j = 0; j < 8; j++) {
                ulonglong2 w = wp[j];
                acc[2 * j]     = fma2(s2, w.x, acc[2 * j]);
                acc[2 * j + 1] = fma2(s2, w.y, acc[2 * j + 1]);
            }
        }
    }

    float outv[FOUTN];
    #pragma unroll
    for (int i = 0; i < 16; i++) {
        float2 v = unpack2(acc[i]);
        outv[2 * i] = v.x; outv[2 * i + 1] = v.y;
    }
    float4* dst = (float4*)(g_h + (size_t)n * FOUTN);
    #pragma unroll
    for (int j = 0; j < 8; j++) {
        float4 o4; float v;
        v = outv[4*j+0] * s_scale[4*j+0] + s_shift[4*j+0]; o4.x = v / (1.f + __expf(-v));
        v = outv[4*j+1] * s_scale[4*j+1] + s_shift[4*j+1]; o4.y = v / (1.f + __expf(-v));
        v = outv[4*j+2] * s_scale[4*j+2] + s_shift[4*j+2]; o4.z = v / (1.f + __expf(-v));
        v = outv[4*j+3] * s_scale[4*j+3] + s_shift[4*j+3]; o4.w = v / (1.f + __expf(-v));
        dst[j] = o4;
    }
}

// ============================================================================
// Stage 2 (mma.sync 3xTF32): M32 per warp. D[256,32] = sum_k Hg_k @ w2[k]
// 256 thr, 8 warps x 32 rows; single A-buffer, 2-phase per k; B pre-split.
// ============================================================================
#define S2T   256
#define TILE  256
#define RST   36
// smem float offsets
#define OFF_BUF 0                    // 256*36 = 9216
#define OFF_IDX 9216                 // 256*27 = 6912 ints
#define OFF_ZW  (9216 + 6912)        // 96
#define OFF_ZB  (OFF_ZW + 96)       // 32
#define S2FLOATS (OFF_ZB + 32)
#define S2BYTES  (S2FLOATS * 4)      // 65024

__global__ __launch_bounds__(S2T, 2)
void stage2_mma(const float* __restrict__ z_feats,
                const int*   __restrict__ nbr,
                const float* __restrict__ mlp_w,
                const float* __restrict__ mlp_b,
                const float* __restrict__ mlp_gamma,
                const float* __restrict__ mlp_beta,
                const float* __restrict__ mlp_mean,
                const float* __restrict__ mlp_var,
                float* __restrict__ out,
                int N, int copies)
{
    extern __shared__ __align__(16) float sm[];
    float* buf  = sm + OFF_BUF;
    int*   idxa = (int*)(sm + OFF_IDX);
    float* zw   = sm + OFF_ZW;
    float* zb   = sm + OFF_ZB;

    const int t = threadIdx.x;
    const int base = blockIdx.x * TILE;

    // preload all indices (256 nodes x 27) coalesced
    {
        const int4* nb4 = (const int4*)(nbr + (size_t)base * KK);
        #pragma unroll
        for (int i = 0; i < 7; i++) {
            int e = t + i * 256;
            if (e < (TILE * KK) / 4) ((int4*)idxa)[e] = nb4[e];
        }
    }
    if (t < FOUTN) {
        float sc = mlp_gamma[t] * rsqrtf(mlp_var[t] + EPSB);
        float sh = mlp_beta[t] - mlp_mean[t] * sc;
        zb[t] = mlp_b[t] * sc + sh;
        #pragma unroll
        for (int f = 0; f < FINN; f++)
            zw[f * FOUTN + t] = mlp_w[f * FOUTN + t] * sc;
    }
    __syncthreads();

    const int w    = t >> 5;
    const int lane = t & 31;
    const int g    = lane >> 2;
    const int tig  = lane & 3;
    const int row0 = w * 32 + g;      // tile0 rows: row0, row0+8; tile1: +16, +24

    float d[2][4][4];
    #pragma unroll
    for (int ti = 0; ti < 2; ti++)
        #pragma unroll
        for (int j = 0; j < 4; j++)
            #pragma unroll
            for (int i = 0; i < 4; i++) d[ti][j][i] = 0.f;

    #pragma unroll 1
    for (int k = 0; k < KK; k++) {
        // ---- gather phase: 8 segs/thread in 2 chunks of 4 (transient regs)
        #pragma unroll
        for (int c4 = 0; c4 < 2; c4++) {
            float4 tmp[4];
            #pragma unroll
            for (int q = 0; q < 4; q++) {
                int s = (c4 * 4 + q) * 256 + t, r = s >> 3, gs = s & 7;
                int idx = idxa[r * KK + k];
                tmp[q] = ((const float4*)(g_h + (size_t)idx * FOUTN))[gs];
            }
            #pragma unroll
            for (int q = 0; q < 4; q++) {
                int s = (c4 * 4 + q) * 256 + t, r = s >> 3, gs = s & 7;
                *(float4*)(buf + r * RST + gs * 4) = tmp[q];
            }
        }
        __syncthreads();

        // ---- compute phase
        #pragma unroll
        for (int fc = 0; fc < 4; fc++) {
            const int cbase = fc * 8 + tig;
            // tile0 A frags
            float a0f = buf[row0 * RST + cbase];
            float a1f = buf[(row0 + 8) * RST + cbase];
            float a2f = buf[row0 * RST + cbase + 4];
            float a3f = buf[(row0 + 8) * RST + cbase + 4];
            // tile1 A frags
            float c0f = buf[(row0 + 16) * RST + cbase];
            float c1f = buf[(row0 + 24) * RST + cbase];
            float c2f = buf[(row0 + 16) * RST + cbase + 4];
            float c3f = buf[(row0 + 24) * RST + cbase + 4];

            unsigned ah0, al0, ah1, al1, ah2, al2, ah3, al3;
            unsigned ch0, cl0, ch1, cl1, ch2, cl2, ch3, cl3;
            split32(a0f, ah0, al0); split32(a1f, ah1, al1);
            split32(a2f, ah2, al2); split32(a3f, ah3, al3);
            split32(c0f, ch0, cl0); split32(c1f, ch1, cl1);
            split32(c2f, ch2, cl2); split32(c3f, ch3, cl3);

            const int e0 = (k * 32 + cbase) * 8 + g;       // f = cbase
            const int e1 = (k * 32 + cbase + 4) * 8 + g;   // f = cbase+4
            float4 bh0 = __ldg((const float4*)g_w2hi + e0);
            float4 bh1 = __ldg((const float4*)g_w2hi + e1);
            float4 bl0 = __ldg((const float4*)g_w2lo + e0);
            float4 bl1 = __ldg((const float4*)g_w2lo + e1);
            const float* bh0a = &bh0.x; const float* bh1a = &bh1.x;
            const float* bl0a = &bl0.x; const float* bl1a = &bl1.x;

            #pragma unroll
            for (int j = 0; j < 4; j++) {
                unsigned b0h = __float_as_uint(bh0a[j]);
                unsigned b1h = __float_as_uint(bh1a[j]);
                unsigned b0l = __float_as_uint(bl0a[j]);
                unsigned b1l = __float_as_uint(bl1a[j]);
                mma_tf32(d[0][j], ah0, ah1, ah2, ah3, b0h, b1h);
                mma_tf32(d[1][j], ch0, ch1, ch2, ch3, b0h, b1h);
                mma_tf32(d[0][j], ah0, ah1, ah2, ah3, b0l, b1l);
                mma_tf32(d[1][j], ch0, ch1, ch2, ch3, b0l, b1l);
                mma_tf32(d[0][j], al0, al1, al2, al3, b0h, b1h);
                mma_tf32(d[1][j], cl0, cl1, cl2, cl3, b0h, b1h);
            }
        }
        __syncthreads();     // buf consumed; next gather may overwrite
    }

    // ---- epilogue: 4 rows per thread-quad position
    #pragma unroll
    for (int ti = 0; ti < 2; ti++) {
        const int n0 = base + row0 + ti * 16;
        const int n1 = n0 + 8;
        const float* zr0 = z_feats + (size_t)n0 * FINN;
        const float* zr1 = z_feats + (size_t)n1 * FINN;
        float z00 = zr0[0], z01 = zr0[1], z02 = zr0[2];
        float z10 = zr1[0], z11 = zr1[1], z12 = zr1[2];

        #pragma unroll
        for (int j = 0; j < 4; j++) {
            int c = 8 * j + 2 * tig;
            float zw0c = zw[c],     zw1c = zw[FOUTN + c],     zw2c = zw[2*FOUTN + c],     zbc = zb[c];
            float zw0d = zw[c + 1], zw1d = zw[FOUTN + c + 1], zw2d = zw[2*FOUTN + c + 1], zbd = zb[c + 1];

            float2 o0, o1;
            o0.x = d[ti][j][0] + fmaxf(z00 * zw0c + z01 * zw1c + z02 * zw2c + zbc, 0.f);
            o0.y = d[ti][j][1] + fmaxf(z00 * zw0d + z01 * zw1d + z02 * zw2d + zbd, 0.f);
            o1.x = d[ti][j][2] + fmaxf(z10 * zw0c + z11 * zw1c + z12 * zw2c + zbc, 0.f);
            o1.y = d[ti][j][3] + fmaxf(z10 * zw0d + z11 * zw1d + z12 * zw2d + zbd, 0.f);

            *(float2*)(out + (size_t)n0 * FOUTN + c) = o0;
            *(float2*)(out + (size_t)n1 * FOUTN + c) = o1;
            if (copies > 1) {
                *(float2*)(out + (size_t)N * FOUTN + (size_t)n0 * FOUTN + c) = o0;
                *(float2*)(out + (size_t)N * FOUTN + (size_t)n1 * FOUTN + c) = o1;
            }
        }
    }
}

extern "C" void kernel_launch(void* const* d_in, const int* in_sizes, int n_in,
                              void* d_out, int out_size) {
    const float* x_feats   = (const float*)d_in[0];
    const float* z_feats   = (const float*)d_in[1];
    const int*   nbr       = (const int*)d_in[2];
    const float* w1        = (const float*)d_in[3];
    const float* bn1_gamma = (const float*)d_in[4];
    const float* bn1_beta  = (const float*)d_in[5];
    const float* bn1_mean  = (const float*)d_in[6];
    const float* bn1_var   = (const float*)d_in[7];
    const float* w2        = (const float*)d_in[8];
    const float* mlp_w     = (const float*)d_in[9];
    const float* mlp_b     = (const float*)d_in[10];
    const float* mlp_gamma = (const float*)d_in[11];
    const float* mlp_beta  = (const float*)d_in[12];
    const float* mlp_mean  = (const float*)d_in[13];
    const float* mlp_var   = (const float*)d_in[14];

    const int N = in_sizes[0] / FINN;
    const int copies = out_size / (N * FOUTN);

    static int cfg_done = 0;
    if (!cfg_done) {
        (void)cudaFuncSetAttribute(stage2_mma,
                                   cudaFuncAttributeMaxDynamicSharedMemorySize,
                                   S2BYTES);
        cfg_done = 1;
    }

    stage1_kernel<<<N / 256, 256>>>(x_feats, nbr, w1,
                                    bn1_gamma, bn1_beta, bn1_mean, bn1_var, w2);
    stage2_mma<<<N / TILE, S2T, S2BYTES>>>(z_feats, nbr,
                                           mlp_w, mlp_b, mlp_gamma, mlp_beta,
                                           mlp_mean, mlp_var,
                                           (float*)d_out, N, copies);
}